// round 8
// baseline (speedup 1.0000x reference)
#include <cuda_runtime.h>
#include <cuda_fp16.h>
#include <mma.h>
#include <math.h>
#include <stdint.h>

using namespace nvcuda;

// ---------------- problem constants ----------------
#define NBOX   1000
#define FH     38
#define FW     50
#define FC     512
#define FC4    128
#define CROP   14
#define RS     7
#define DFLAT  25088        // 7*7*512
#define D1     4096
#define NCLS   21
#define NREG   80

// ---------------- scratch (device globals; no allocations allowed) ----------
__device__ __half g_pooledh[(size_t)NBOX * DFLAT];  // 50 MB, fp16 A of GEMM1
__device__ __half g_w1h[(size_t)DFLAT * D1];        // 205 MB, fp16 W1 [K][N]
__device__ __half g_w2h[(size_t)D1 * D1];           // 33.5 MB, fp16 W2 [K][N]
__device__ __half g_x1h[(size_t)NBOX * D1];         // fp16 A of GEMM2
__device__ float  g_x2[(size_t)NBOX * D1];          // fp32, heads input

// ---------------- helpers ----------------
__device__ __forceinline__ uint32_t smem_u32(const void* p) {
    uint32_t a;
    asm("{ .reg .u64 t; cvta.to.shared.u64 t, %1; cvt.u32.u64 %0, t; }" : "=r"(a) : "l"(p));
    return a;
}
__device__ __forceinline__ void cp_async16(uint32_t dst, const void* src, int sz) {
    asm volatile("cp.async.cg.shared.global [%0], [%1], 16, %2;" :: "r"(dst), "l"(src), "r"(sz));
}
#define CP_COMMIT() asm volatile("cp.async.commit_group;" ::: "memory")
#define CP_WAIT(n)  asm volatile("cp.async.wait_group %0;" :: "n"(n) : "memory")

// ===================== Kernel 1: fused prep =================================
// blocks [0, NBOX)                 : roi_pool (latency-bound, overlaps converts)
// blocks [NBOX, NBOX+W1B)          : W1 fp32->fp16
// blocks [NBOX+W1B, NBOX+W1B+W2B)  : W2 fp32->fp16
#define W1N4 (((size_t)DFLAT * D1) / 4)
#define W2N4 (((size_t)D1 * D1) / 4)
#define W1B  ((unsigned)((W1N4 + 255) / 256))
#define W2B  ((unsigned)((W2N4 + 255) / 256))

__device__ __forceinline__ void convert_body(const float* __restrict__ src,
                                             __half* __restrict__ dst,
                                             size_t n4, unsigned blk)
{
    size_t i = (size_t)blk * 256 + threadIdx.x;
    if (i < n4) {
        float4 v = reinterpret_cast<const float4*>(src)[i];
        __half2* d = reinterpret_cast<__half2*>(dst) + 2 * i;
        d[0] = __floats2half2_rn(v.x, v.y);
        d[1] = __floats2half2_rn(v.z, v.w);
    }
}

__global__ __launch_bounds__(256) void prep_kernel(
    const float* __restrict__ feats, const float* __restrict__ boxes,
    const float* __restrict__ W1, const float* __restrict__ W2)
{
    unsigned b = blockIdx.x;
    if (b >= NBOX) {                       // converts
        if (b < NBOX + W1B) convert_body(W1, g_w1h, W1N4, b - NBOX);
        else                convert_body(W2, g_w2h, W2N4, b - NBOX - W1B);
        return;
    }
    // ---- roi_pool for box n = b ----
    int n = b;
    __shared__ int   sy0[CROP], sy1[CROP], sx0[CROP], sx1[CROP];
    __shared__ float swy[CROP], swx[CROP];

    int t = threadIdx.x;
    if (t < 2 * CROP) {
        int  i   = t % CROP;
        bool isY = (t < CROP);
        float b1 = boxes[n * 4 + (isY ? 0 : 1)];
        float b2 = boxes[n * 4 + (isY ? 2 : 3)];
        float S  = isY ? (float)(FH - 1) : (float)(FW - 1);
        int   lim = isY ? (FH - 1) : (FW - 1);
        float v  = b1 * S + (float)i * ((b2 - b1) * S / (float)(CROP - 1));
        float f  = floorf(v);
        int i0 = (int)f;
        i0 = min(max(i0, 0), lim);
        int i1 = min(i0 + 1, lim);
        float w = v - f;
        if (isY) { sy0[i] = i0; sy1[i] = i1; swy[i] = w; }
        else     { sx0[i] = i0; sx1[i] = i1; swx[i] = w; }
    }
    __syncthreads();

    const float4* F4 = reinterpret_cast<const float4*>(feats);
    __half2* H2 = reinterpret_cast<__half2*>(g_pooledh);

    for (int idx = t; idx < RS * RS * FC4; idx += 256) {
        int c4 = idx & (FC4 - 1);
        int p  = idx >> 7;
        int px = p % RS;
        int py = p / RS;

        float4 best = make_float4(-3.4e38f, -3.4e38f, -3.4e38f, -3.4e38f);
        #pragma unroll
        for (int dy = 0; dy < 2; dy++) {
            int iy = 2 * py + dy;
            int y0 = sy0[iy], y1 = sy1[iy];
            float wy = swy[iy], omwy = 1.f - wy;
            #pragma unroll
            for (int dx = 0; dx < 2; dx++) {
                int ix = 2 * px + dx;
                int x0 = sx0[ix], x1 = sx1[ix];
                float wx = swx[ix], omwx = 1.f - wx;
                float4 a = F4[(y0 * FW + x0) * FC4 + c4];
                float4 bb = F4[(y0 * FW + x1) * FC4 + c4];
                float4 c = F4[(y1 * FW + x0) * FC4 + c4];
                float4 d = F4[(y1 * FW + x1) * FC4 + c4];
                float4 v;
                v.x = (a.x * omwx + bb.x * wx) * omwy + (c.x * omwx + d.x * wx) * wy;
                v.y = (a.y * omwx + bb.y * wx) * omwy + (c.y * omwx + d.y * wx) * wy;
                v.z = (a.z * omwx + bb.z * wx) * omwy + (c.z * omwx + d.z * wx) * wy;
                v.w = (a.w * omwx + bb.w * wx) * omwy + (c.w * omwx + d.w * wx) * wy;
                best.x = fmaxf(best.x, v.x);
                best.y = fmaxf(best.y, v.y);
                best.z = fmaxf(best.z, v.z);
                best.w = fmaxf(best.w, v.w);
            }
        }
        size_t base = (size_t)n * DFLAT + (size_t)p * FC + c4 * 4;
        H2[base / 2]     = __floats2half2_rn(best.x, best.y);
        H2[base / 2 + 1] = __floats2half2_rn(best.z, best.w);
    }
}

// ===================== Kernel 2: fp16 wmma GEMM + bias + relu ===============
// C[M,N] = relu(A[M,K] @ B[K,N] + bias). A,B fp16 row-major, fp32 accum.
// 128x256x32 CTA tile, 4-stage cp.async pipeline, 8 warps (2M x 4N, 64x64 each).
#define GNS 4
#define BM 128
#define BN 256
#define BK 32
#define APAD 8
#define BPAD 8
#define AS_STRIDE (BK + APAD)                 // 40 halves (80 B)
#define BS_STRIDE (BN + BPAD)                 // 264 halves (528 B, 16B-mult)
#define A_TILE_BYTES (BM * AS_STRIDE * 2)     // 10240
#define B_TILE_BYTES (BK * BS_STRIDE * 2)     // 16896
#define STAGE_BYTES  (A_TILE_BYTES + B_TILE_BYTES)   // 27136
#define GEMM_DSMEM   (GNS * STAGE_BYTES)      // 108544

__global__ __launch_bounds__(256, 1) void gemm_fp16_kernel(
    const __half* __restrict__ A, const __half* __restrict__ B,
    const float* __restrict__ bias, void* __restrict__ Cv,
    int M, int N, int K, int half_out)
{
    extern __shared__ char dsm[];
    int tid = threadIdx.x, warpId = tid >> 5, lane = tid & 31;
    int m0 = blockIdx.y * BM, n0 = blockIdx.x * BN;
    int wm = warpId & 1;      // 2 M-groups of 64
    int wn = warpId >> 1;     // 4 N-groups of 64
    const int KT = K / BK;

    wmma::fragment<wmma::accumulator, 16, 16, 16, float> acc[4][4];
    #pragma unroll
    for (int i = 0; i < 4; i++)
        #pragma unroll
        for (int j = 0; j < 4; j++)
            wmma::fill_fragment(acc[i][j], 0.0f);

    auto load_tile = [&](int j) {
        char* st = dsm + (j & (GNS - 1)) * STAGE_BYTES;
        uint32_t sA = smem_u32(st);
        uint32_t sB = sA + A_TILE_BYTES;
        int kb = j * BK;
        // A tile: 128 rows x 32 halves = 512 x 16B (4 chunks/row)
        #pragma unroll
        for (int i = 0; i < 2; i++) {
            int idx = i * 256 + tid;
            int row = idx >> 2, c = idx & 3;
            int gm = m0 + row;
            const __half* src = A + (size_t)min(gm, M - 1) * K + kb + c * 8;
            cp_async16(sA + row * (AS_STRIDE * 2) + c * 16, src, (gm < M) ? 16 : 0);
        }
        // B tile: 32 rows x 256 halves = 1024 x 16B (32 chunks/row)
        #pragma unroll
        for (int i = 0; i < 4; i++) {
            int idx = i * 256 + tid;
            int row = idx >> 5, c = idx & 31;
            const __half* src = B + (size_t)(kb + row) * N + n0 + c * 8;
            cp_async16(sB + row * (BS_STRIDE * 2) + c * 16, src, 16);
        }
        CP_COMMIT();
    };

    // prologue: stages 0..2
    for (int j = 0; j < GNS - 1; j++) load_tile(j);

    for (int it = 0; it < KT; it++) {
        CP_WAIT(GNS - 2);          // stage `it` resident (exactly 1 commit/iter)
        __syncthreads();

        int j = it + GNS - 1;
        if (j < KT) load_tile(j);
        else        CP_COMMIT();   // empty group keeps wait_group counting exact

        const char* st = dsm + (it & (GNS - 1)) * STAGE_BYTES;
        const __half* sA = reinterpret_cast<const __half*>(st);
        const __half* sB = reinterpret_cast<const __half*>(st + A_TILE_BYTES);

        #pragma unroll
        for (int kk = 0; kk < BK; kk += 16) {
            wmma::fragment<wmma::matrix_a, 16, 16, 16, __half, wmma::row_major> af[4];
            wmma::fragment<wmma::matrix_b, 16, 16, 16, __half, wmma::row_major> bf[4];
            #pragma unroll
            for (int i = 0; i < 4; i++)
                wmma::load_matrix_sync(af[i], sA + (wm * 64 + i * 16) * AS_STRIDE + kk, AS_STRIDE);
            #pragma unroll
            for (int j2 = 0; j2 < 4; j2++)
                wmma::load_matrix_sync(bf[j2], sB + kk * BS_STRIDE + wn * 64 + j2 * 16, BS_STRIDE);
            #pragma unroll
            for (int i = 0; i < 4; i++)
                #pragma unroll
                for (int j2 = 0; j2 < 4; j2++)
                    wmma::mma_sync(acc[i][j2], af[i], bf[j2], acc[i][j2]);
        }
    }

    // epilogue: stage per-warp through (reused) dynamic smem, ldm=20 (16B-mult)
    __syncthreads();
    float* stg = reinterpret_cast<float*>(dsm) + warpId * 16 * 20;
    #pragma unroll
    for (int i = 0; i < 4; i++) {
        #pragma unroll
        for (int j2 = 0; j2 < 4; j2++) {
            wmma::store_matrix_sync(stg, acc[i][j2], 20, wmma::mem_row_major);
            __syncwarp();
            #pragma unroll
            for (int e = lane; e < 256; e += 32) {
                int r = e >> 4, cc = e & 15;
                int gm = m0 + wm * 64 + i * 16 + r;
                int gn = n0 + wn * 64 + j2 * 16 + cc;
                if (gm < M) {
                    float v = fmaxf(stg[r * 20 + cc] + bias[gn], 0.0f);
                    if (half_out)
                        reinterpret_cast<__half*>(Cv)[(size_t)gm * N + gn] = __float2half_rn(v);
                    else
                        reinterpret_cast<float*>(Cv)[(size_t)gm * N + gn] = v;
                }
            }
            __syncwarp();
        }
    }
}

// ===================== Kernel 3: heads, 8 boxes per block ===================
#define HB  8
#define HCH 512
__global__ __launch_bounds__(256) void heads_kernel(
    const float* __restrict__ Wc, const float* __restrict__ bc,
    const float* __restrict__ Wr, const float* __restrict__ br,
    float* __restrict__ out)
{
    int n0 = blockIdx.x * HB;
    __shared__ float xs[HB][HCH];
    __shared__ float part[2][HB][104];
    __shared__ float res[HB][104];

    int t = threadIdx.x, wid = t >> 5, lane = t & 31;
    int h = wid >> 2, grp = wid & 3;
    int c = grp * 32 + lane;                 // output column (valid < 101)
    float acc[HB];
    #pragma unroll
    for (int b = 0; b < HB; b++) acc[b] = 0.f;

    for (int ci = 0; ci < D1 / HCH; ci++) {
        __syncthreads();
        int k0 = ci * HCH;
        #pragma unroll
        for (int i = 0; i < 4; i++) {        // 1024 float4 loads
            int idx = i * 256 + t;
            int b = idx >> 7;
            int o = idx & 127;
            reinterpret_cast<float4*>(&xs[b][0])[o] =
                reinterpret_cast<const float4*>(g_x2 + (size_t)(n0 + b) * D1 + k0)[o];
        }
        __syncthreads();
        if (c < NCLS + NREG) {
            int kk0 = h * (HCH / 2);
            if (c < NCLS) {
                const float* wp = Wc + (size_t)(k0 + kk0) * NCLS + c;
                #pragma unroll 4
                for (int k = 0; k < HCH / 2; k++) {
                    float w = wp[(size_t)k * NCLS];
                    #pragma unroll
                    for (int b = 0; b < HB; b++) acc[b] += xs[b][kk0 + k] * w;
                }
            } else {
                const float* wp = Wr + (size_t)(k0 + kk0) * NREG + (c - NCLS);
                #pragma unroll 4
                for (int k = 0; k < HCH / 2; k++) {
                    float w = wp[(size_t)k * NREG];
                    #pragma unroll
                    for (int b = 0; b < HB; b++) acc[b] += xs[b][kk0 + k] * w;
                }
            }
        }
    }
    if (c < NCLS + NREG) {
        #pragma unroll
        for (int b = 0; b < HB; b++) part[h][b][c] = acc[b];
    }
    __syncthreads();

    if (wid < HB) {
        int b = wid;
        #pragma unroll
        for (int j = 0; j < 4; j++) {
            int cc = lane + j * 32;
            if (cc < NCLS + NREG) {
                float v = part[0][b][cc] + part[1][b][cc]
                        + (cc < NCLS ? bc[cc] : br[cc - NCLS]);
                res[b][cc] = v;
                if (cc >= NCLS)
                    out[(size_t)NBOX * NCLS + (size_t)(n0 + b) * NREG + (cc - NCLS)] = v;
            }
        }
        __syncwarp();
        float v = (lane < NCLS) ? res[b][lane] : -3.4e38f;
        float m = v;
        #pragma unroll
        for (int o = 16; o; o >>= 1) m = fmaxf(m, __shfl_xor_sync(0xffffffff, m, o));
        float e = (lane < NCLS) ? expf(v - m) : 0.f;
        float ssum = e;
        #pragma unroll
        for (int o = 16; o; o >>= 1) ssum += __shfl_xor_sync(0xffffffff, ssum, o);
        if (lane < NCLS)
            out[(size_t)(n0 + b) * NCLS + lane] = e / ssum;
    }
}

// ===================== launcher ============================================
extern "C" void kernel_launch(void* const* d_in, const int* in_sizes, int n_in,
                              void* d_out, int out_size)
{
    const float* feats = (const float*)d_in[0];
    const float* boxes = (const float*)d_in[1];
    const float* W1    = (const float*)d_in[2];
    const float* b1    = (const float*)d_in[3];
    const float* W2    = (const float*)d_in[4];
    const float* b2    = (const float*)d_in[5];
    const float* Wc    = (const float*)d_in[6];
    const float* bc    = (const float*)d_in[7];
    const float* Wr    = (const float*)d_in[8];
    const float* br    = (const float*)d_in[9];
    float* out = (float*)d_out;

    __half* w1h;  cudaGetSymbolAddress((void**)&w1h, g_w1h);
    __half* w2h;  cudaGetSymbolAddress((void**)&w2h, g_w2h);
    __half* ph;   cudaGetSymbolAddress((void**)&ph,  g_pooledh);
    __half* x1h;  cudaGetSymbolAddress((void**)&x1h, g_x1h);
    float*  x2;   cudaGetSymbolAddress((void**)&x2,  g_x2);

    cudaFuncSetAttribute(gemm_fp16_kernel,
                         cudaFuncAttributeMaxDynamicSharedMemorySize, GEMM_DSMEM);

    prep_kernel<<<NBOX + W1B + W2B, 256>>>(feats, boxes, W1, W2);

    dim3 g1(D1 / BN, (NBOX + BM - 1) / BM);   // (16, 8) = 128 CTAs, one wave
    gemm_fp16_kernel<<<g1, 256, GEMM_DSMEM>>>(ph,  w1h, b1, x1h, NBOX, D1, DFLAT, 1);
    gemm_fp16_kernel<<<g1, 256, GEMM_DSMEM>>>(x1h, w2h, b2, x2,  NBOX, D1, D1,    0);

    heads_kernel<<<NBOX / HB, 256>>>(Wc, bc, Wr, br, out);
}

// round 9
// speedup vs baseline: 1.3145x; 1.3145x over previous
#include <cuda_runtime.h>
#include <cuda_fp16.h>
#include <mma.h>
#include <math.h>
#include <stdint.h>

using namespace nvcuda;

// ---------------- problem constants ----------------
#define NBOX   1000
#define FH     38
#define FW     50
#define FC     512
#define FC4    128
#define CROP   14
#define RS     7
#define DFLAT  25088        // 7*7*512
#define D1     4096
#define NCLS   21
#define NREG   80
#define NOUT   101          // NCLS + NREG

// ---------------- scratch (device globals; no allocations allowed) ----------
__device__ __half g_pooledh[(size_t)NBOX * DFLAT];  // 50 MB
__device__ __half g_w1h[(size_t)DFLAT * D1];        // 205 MB
__device__ __half g_w2h[(size_t)D1 * D1];           // 33.5 MB
__device__ __half g_x1h[(size_t)NBOX * D1];
__device__ float  g_x2[(size_t)NBOX * D1];
__device__ float  g_headpart[8][(size_t)NBOX * 128];  // split-K partials, 4 MB

// ---------------- helpers ----------------
__device__ __forceinline__ uint32_t smem_u32(const void* p) {
    uint32_t a;
    asm("{ .reg .u64 t; cvta.to.shared.u64 t, %1; cvt.u32.u64 %0, t; }" : "=r"(a) : "l"(p));
    return a;
}
__device__ __forceinline__ void cp_async16(uint32_t dst, const void* src, int sz) {
    asm volatile("cp.async.cg.shared.global [%0], [%1], 16, %2;" :: "r"(dst), "l"(src), "r"(sz));
}
#define CP_COMMIT() asm volatile("cp.async.commit_group;" ::: "memory")
#define CP_WAIT(n)  asm volatile("cp.async.wait_group %0;" :: "n"(n) : "memory")

// ===================== Kernel 1: fused prep =================================
#define W1N4 (((size_t)DFLAT * D1) / 4)
#define W2N4 (((size_t)D1 * D1) / 4)
#define W1B  ((unsigned)((W1N4 + 255) / 256))
#define W2B  ((unsigned)((W2N4 + 255) / 256))

__device__ __forceinline__ void convert_body(const float* __restrict__ src,
                                             __half* __restrict__ dst,
                                             size_t n4, unsigned blk)
{
    size_t i = (size_t)blk * 256 + threadIdx.x;
    if (i < n4) {
        float4 v = reinterpret_cast<const float4*>(src)[i];
        __half2* d = reinterpret_cast<__half2*>(dst) + 2 * i;
        d[0] = __floats2half2_rn(v.x, v.y);
        d[1] = __floats2half2_rn(v.z, v.w);
    }
}

__global__ __launch_bounds__(256) void prep_kernel(
    const float* __restrict__ feats, const float* __restrict__ boxes,
    const float* __restrict__ W1, const float* __restrict__ W2)
{
    unsigned b = blockIdx.x;
    if (b >= NBOX) {
        if (b < NBOX + W1B) convert_body(W1, g_w1h, W1N4, b - NBOX);
        else                convert_body(W2, g_w2h, W2N4, b - NBOX - W1B);
        return;
    }
    int n = b;
    __shared__ int   sy0[CROP], sy1[CROP], sx0[CROP], sx1[CROP];
    __shared__ float swy[CROP], swx[CROP];

    int t = threadIdx.x;
    if (t < 2 * CROP) {
        int  i   = t % CROP;
        bool isY = (t < CROP);
        float b1 = boxes[n * 4 + (isY ? 0 : 1)];
        float b2 = boxes[n * 4 + (isY ? 2 : 3)];
        float S  = isY ? (float)(FH - 1) : (float)(FW - 1);
        int   lim = isY ? (FH - 1) : (FW - 1);
        float v  = b1 * S + (float)i * ((b2 - b1) * S / (float)(CROP - 1));
        float f  = floorf(v);
        int i0 = (int)f;
        i0 = min(max(i0, 0), lim);
        int i1 = min(i0 + 1, lim);
        float w = v - f;
        if (isY) { sy0[i] = i0; sy1[i] = i1; swy[i] = w; }
        else     { sx0[i] = i0; sx1[i] = i1; swx[i] = w; }
    }
    __syncthreads();

    const float4* F4 = reinterpret_cast<const float4*>(feats);
    __half2* H2 = reinterpret_cast<__half2*>(g_pooledh);

    for (int idx = t; idx < RS * RS * FC4; idx += 256) {
        int c4 = idx & (FC4 - 1);
        int p  = idx >> 7;
        int px = p % RS;
        int py = p / RS;

        float4 best = make_float4(-3.4e38f, -3.4e38f, -3.4e38f, -3.4e38f);
        #pragma unroll
        for (int dy = 0; dy < 2; dy++) {
            int iy = 2 * py + dy;
            int y0 = sy0[iy], y1 = sy1[iy];
            float wy = swy[iy], omwy = 1.f - wy;
            #pragma unroll
            for (int dx = 0; dx < 2; dx++) {
                int ix = 2 * px + dx;
                int x0 = sx0[ix], x1 = sx1[ix];
                float wx = swx[ix], omwx = 1.f - wx;
                float4 a = F4[(y0 * FW + x0) * FC4 + c4];
                float4 bb = F4[(y0 * FW + x1) * FC4 + c4];
                float4 c = F4[(y1 * FW + x0) * FC4 + c4];
                float4 d = F4[(y1 * FW + x1) * FC4 + c4];
                float4 v;
                v.x = (a.x * omwx + bb.x * wx) * omwy + (c.x * omwx + d.x * wx) * wy;
                v.y = (a.y * omwx + bb.y * wx) * omwy + (c.y * omwx + d.y * wx) * wy;
                v.z = (a.z * omwx + bb.z * wx) * omwy + (c.z * omwx + d.z * wx) * wy;
                v.w = (a.w * omwx + bb.w * wx) * omwy + (c.w * omwx + d.w * wx) * wy;
                best.x = fmaxf(best.x, v.x);
                best.y = fmaxf(best.y, v.y);
                best.z = fmaxf(best.z, v.z);
                best.w = fmaxf(best.w, v.w);
            }
        }
        size_t base = (size_t)n * DFLAT + (size_t)p * FC + c4 * 4;
        H2[base / 2]     = __floats2half2_rn(best.x, best.y);
        H2[base / 2 + 1] = __floats2half2_rn(best.z, best.w);
    }
}

// ===================== Kernel 2: fp16 wmma GEMM (round-7 proven config) =====
#define GNS 4
#define BM 128
#define BN 128
#define BK 32
#define APAD 8
#define BPAD 8
#define AS_STRIDE (BK + APAD)                 // 40 halves
#define BS_STRIDE (BN + BPAD)                 // 136 halves
#define A_TILE_BYTES (BM * AS_STRIDE * 2)     // 10240
#define B_TILE_BYTES (BK * BS_STRIDE * 2)     // 8704
#define STAGE_BYTES  (A_TILE_BYTES + B_TILE_BYTES)   // 18944
#define GEMM_DSMEM   (GNS * STAGE_BYTES)      // 75776

__global__ __launch_bounds__(256, 2) void gemm_fp16_kernel(
    const __half* __restrict__ A, const __half* __restrict__ B,
    const float* __restrict__ bias, void* __restrict__ Cv,
    int M, int N, int K, int half_out)
{
    extern __shared__ char dsm[];
    int tid = threadIdx.x, warpId = tid >> 5, lane = tid & 31;
    int m0 = blockIdx.y * BM, n0 = blockIdx.x * BN;
    int wm = warpId & 1;      // 2 M-groups of 64
    int wn = warpId >> 1;     // 4 N-groups of 32
    const int KT = K / BK;

    wmma::fragment<wmma::accumulator, 16, 16, 16, float> acc[4][2];
    #pragma unroll
    for (int i = 0; i < 4; i++)
        #pragma unroll
        for (int j = 0; j < 2; j++)
            wmma::fill_fragment(acc[i][j], 0.0f);

    auto load_tile = [&](int j) {
        char* st = dsm + (j & (GNS - 1)) * STAGE_BYTES;
        uint32_t sA = smem_u32(st);
        uint32_t sB = sA + A_TILE_BYTES;
        int kb = j * BK;
        #pragma unroll
        for (int i = 0; i < 2; i++) {
            int idx = i * 256 + tid;
            int row = idx >> 2, c = idx & 3;
            int gm = m0 + row;
            const __half* src = A + (size_t)min(gm, M - 1) * K + kb + c * 8;
            cp_async16(sA + row * (AS_STRIDE * 2) + c * 16, src, (gm < M) ? 16 : 0);
        }
        #pragma unroll
        for (int i = 0; i < 2; i++) {
            int idx = i * 256 + tid;
            int row = idx >> 4, c = idx & 15;
            const __half* src = B + (size_t)(kb + row) * N + n0 + c * 8;
            cp_async16(sB + row * (BS_STRIDE * 2) + c * 16, src, 16);
        }
        CP_COMMIT();
    };

    for (int j = 0; j < GNS - 1; j++) load_tile(j);

    for (int it = 0; it < KT; it++) {
        CP_WAIT(GNS - 2);
        __syncthreads();

        int j = it + GNS - 1;
        if (j < KT) load_tile(j);
        else        CP_COMMIT();   // keep wait_group counting exact in the tail

        const char* st = dsm + (it & (GNS - 1)) * STAGE_BYTES;
        const __half* sA = reinterpret_cast<const __half*>(st);
        const __half* sB = reinterpret_cast<const __half*>(st + A_TILE_BYTES);

        #pragma unroll
        for (int kk = 0; kk < BK; kk += 16) {
            wmma::fragment<wmma::matrix_a, 16, 16, 16, __half, wmma::row_major> af[4];
            wmma::fragment<wmma::matrix_b, 16, 16, 16, __half, wmma::row_major> bf[2];
            #pragma unroll
            for (int i = 0; i < 4; i++)
                wmma::load_matrix_sync(af[i], sA + (wm * 64 + i * 16) * AS_STRIDE + kk, AS_STRIDE);
            #pragma unroll
            for (int j2 = 0; j2 < 2; j2++)
                wmma::load_matrix_sync(bf[j2], sB + kk * BS_STRIDE + wn * 32 + j2 * 16, BS_STRIDE);
            #pragma unroll
            for (int i = 0; i < 4; i++)
                #pragma unroll
                for (int j2 = 0; j2 < 2; j2++)
                    wmma::mma_sync(acc[i][j2], af[i], bf[j2], acc[i][j2]);
        }
    }

    __syncthreads();
    float* stg = reinterpret_cast<float*>(dsm) + warpId * 16 * 20;
    #pragma unroll
    for (int i = 0; i < 4; i++) {
        #pragma unroll
        for (int j2 = 0; j2 < 2; j2++) {
            wmma::store_matrix_sync(stg, acc[i][j2], 20, wmma::mem_row_major);
            __syncwarp();
            #pragma unroll
            for (int e = lane; e < 256; e += 32) {
                int r = e >> 4, cc = e & 15;
                int gm = m0 + wm * 64 + i * 16 + r;
                int gn = n0 + wn * 32 + j2 * 16 + cc;
                if (gm < M) {
                    float v = fmaxf(stg[r * 20 + cc] + bias[gn], 0.0f);
                    if (half_out)
                        reinterpret_cast<__half*>(Cv)[(size_t)gm * N + gn] = __float2half_rn(v);
                    else
                        reinterpret_cast<float*>(Cv)[(size_t)gm * N + gn] = v;
                }
            }
            __syncwarp();
        }
    }
}

// ===================== Kernel 3a: heads split-K partials ====================
// grid (NBOX/8, 8). Block (bx, ks): boxes 8bx..8bx+7, K range [512ks, 512ks+512).
// part[ks][n][c] = sum_k x2[n][k] * W[k][c]   (c<101; cols 101..127 zeroed)
__global__ __launch_bounds__(256) void heads_part_kernel(
    const float* __restrict__ Wc, const float* __restrict__ Wr)
{
    int n0 = blockIdx.x * 8;
    int ks = blockIdx.y;
    int k0 = ks * 512;

    __shared__ float xs[8][512];
    __shared__ float red[2][8][128];

    int t = threadIdx.x;
    #pragma unroll
    for (int i = 0; i < 4; i++) {            // 1024 float4 loads
        int idx = i * 256 + t;
        int b = idx >> 7, o = idx & 127;
        reinterpret_cast<float4*>(&xs[b][0])[o] =
            reinterpret_cast<const float4*>(g_x2 + (size_t)(n0 + b) * D1 + k0)[o];
    }
    __syncthreads();

    int c = t & 127;         // output column
    int h = t >> 7;          // 0/1: K sub-half of 256
    int kb = h * 256;
    float acc[8];
    #pragma unroll
    for (int b = 0; b < 8; b++) acc[b] = 0.f;

    if (c < NOUT) {
        if (c < NCLS) {
            const float* wp = Wc + (size_t)(k0 + kb) * NCLS + c;
            #pragma unroll 4
            for (int k = 0; k < 256; k++) {
                float w = wp[(size_t)k * NCLS];
                #pragma unroll
                for (int b = 0; b < 8; b++) acc[b] += xs[b][kb + k] * w;
            }
        } else {
            const float* wp = Wr + (size_t)(k0 + kb) * NREG + (c - NCLS);
            #pragma unroll 4
            for (int k = 0; k < 256; k++) {
                float w = wp[(size_t)k * NREG];
                #pragma unroll
                for (int b = 0; b < 8; b++) acc[b] += xs[b][kb + k] * w;
            }
        }
    }
    #pragma unroll
    for (int b = 0; b < 8; b++) red[h][b][c] = acc[b];
    __syncthreads();

    if (h == 0) {
        #pragma unroll
        for (int b = 0; b < 8; b++)
            g_headpart[ks][(size_t)(n0 + b) * 128 + c] = red[0][b][c] + red[1][b][c];
    }
}

// ===================== Kernel 3b: reduce + bias + softmax + write ===========
// grid NBOX/8, 8 warps/block, warp w -> box n0+w.
__global__ __launch_bounds__(256) void heads_final_kernel(
    const float* __restrict__ bc, const float* __restrict__ br,
    float* __restrict__ out)
{
    int n = blockIdx.x * 8 + (threadIdx.x >> 5);
    int lane = threadIdx.x & 31;

    float v[4];
    #pragma unroll
    for (int j = 0; j < 4; j++) {
        int cc = j * 32 + lane;
        float s = 0.f;
        #pragma unroll
        for (int ks = 0; ks < 8; ks++)
            s += g_headpart[ks][(size_t)n * 128 + cc];
        v[j] = s;
    }
    // reg outputs: columns 21..100
    #pragma unroll
    for (int j = 0; j < 4; j++) {
        int cc = j * 32 + lane;
        if (cc >= NCLS && cc < NOUT)
            out[(size_t)NBOX * NCLS + (size_t)n * NREG + (cc - NCLS)] = v[j] + br[cc - NCLS];
    }
    // softmax over columns 0..20 (all in j=0)
    float cv = (lane < NCLS) ? v[0] + bc[lane] : -3.4e38f;
    float m = cv;
    #pragma unroll
    for (int o = 16; o; o >>= 1) m = fmaxf(m, __shfl_xor_sync(0xffffffff, m, o));
    float e = (lane < NCLS) ? expf(cv - m) : 0.f;
    float ssum = e;
    #pragma unroll
    for (int o = 16; o; o >>= 1) ssum += __shfl_xor_sync(0xffffffff, ssum, o);
    if (lane < NCLS)
        out[(size_t)n * NCLS + lane] = e / ssum;
}

// ===================== launcher ============================================
extern "C" void kernel_launch(void* const* d_in, const int* in_sizes, int n_in,
                              void* d_out, int out_size)
{
    const float* feats = (const float*)d_in[0];
    const float* boxes = (const float*)d_in[1];
    const float* W1    = (const float*)d_in[2];
    const float* b1    = (const float*)d_in[3];
    const float* W2    = (const float*)d_in[4];
    const float* b2    = (const float*)d_in[5];
    const float* Wc    = (const float*)d_in[6];
    const float* bc    = (const float*)d_in[7];
    const float* Wr    = (const float*)d_in[8];
    const float* br    = (const float*)d_in[9];
    float* out = (float*)d_out;

    __half* w1h;  cudaGetSymbolAddress((void**)&w1h, g_w1h);
    __half* w2h;  cudaGetSymbolAddress((void**)&w2h, g_w2h);
    __half* ph;   cudaGetSymbolAddress((void**)&ph,  g_pooledh);
    __half* x1h;  cudaGetSymbolAddress((void**)&x1h, g_x1h);
    float*  x2;   cudaGetSymbolAddress((void**)&x2,  g_x2);

    cudaFuncSetAttribute(gemm_fp16_kernel,
                         cudaFuncAttributeMaxDynamicSharedMemorySize, GEMM_DSMEM);

    prep_kernel<<<NBOX + W1B + W2B, 256>>>(feats, boxes, W1, W2);

    dim3 g1(D1 / BN, (NBOX + BM - 1) / BM);   // (32, 8)
    gemm_fp16_kernel<<<g1, 256, GEMM_DSMEM>>>(ph,  w1h, b1, x1h, NBOX, D1, DFLAT, 1);
    gemm_fp16_kernel<<<g1, 256, GEMM_DSMEM>>>(x1h, w2h, b2, x2,  NBOX, D1, D1,    0);

    heads_part_kernel<<<dim3(NBOX / 8, 8), 256>>>(Wc, Wr);
    heads_final_kernel<<<NBOX / 8, 256>>>(bc, br, out);
}

// round 11
// speedup vs baseline: 1.3428x; 1.0216x over previous
#include <cuda_runtime.h>
#include <cuda_fp16.h>
#include <mma.h>
#include <math.h>
#include <stdint.h>

using namespace nvcuda;

// ---------------- problem constants ----------------
#define NBOX   1000
#define FH     38
#define FW     50
#define FC     512
#define FC4    128
#define CROP   14
#define RS     7
#define DFLAT  25088        // 7*7*512
#define D1     4096
#define NCLS   21
#define NREG   80
#define NOUT   101          // NCLS + NREG
#define NHC    128          // padded head cols

// ---------------- scratch (device globals; no allocations allowed) ----------
__device__ __half g_pooledh[(size_t)NBOX * DFLAT];  // 50 MB
__device__ __half g_w1h[(size_t)DFLAT * D1];        // 205 MB
__device__ __half g_w2h[(size_t)D1 * D1];           // 33.5 MB
__device__ __half g_x1h[(size_t)NBOX * D1];
__device__ __half g_x2h[(size_t)NBOX * D1];         // fp16 heads input
__device__ __half g_wcrh[(size_t)D1 * NHC];         // packed [Wc|Wr|0] fp16, 1 MB
__device__ float  g_bcr[NHC];                       // packed [bc|br|0]
__device__ float  g_logits[(size_t)NBOX * NHC];     // GEMM3 output (bias added)

// ---------------- helpers ----------------
__device__ __forceinline__ uint32_t smem_u32(const void* p) {
    uint32_t a;
    asm("{ .reg .u64 t; cvta.to.shared.u64 t, %1; cvt.u32.u64 %0, t; }" : "=r"(a) : "l"(p));
    return a;
}
__device__ __forceinline__ void cp_async16(uint32_t dst, const void* src, int sz) {
    asm volatile("cp.async.cg.shared.global [%0], [%1], 16, %2;" :: "r"(dst), "l"(src), "r"(sz));
}
#define CP_COMMIT() asm volatile("cp.async.commit_group;" ::: "memory")
#define CP_WAIT(n)  asm volatile("cp.async.wait_group %0;" :: "n"(n) : "memory")

// ===================== Kernel 1: fused prep =================================
// blocks: [0,NBOX) roi_pool | W1 convert | W2 convert | Wcr pack | 1 bias block
#define W1N4 (((size_t)DFLAT * D1) / 4)
#define W2N4 (((size_t)D1 * D1) / 4)
#define W1B  ((unsigned)((W1N4 + 255) / 256))
#define W2B  ((unsigned)((W2N4 + 255) / 256))
#define WCRN (((size_t)D1 * NHC))
#define WCRB ((unsigned)((WCRN + 255) / 256))

__device__ __forceinline__ void convert_body(const float* __restrict__ src,
                                             __half* __restrict__ dst,
                                             size_t n4, unsigned blk)
{
    size_t i = (size_t)blk * 256 + threadIdx.x;
    if (i < n4) {
        float4 v = reinterpret_cast<const float4*>(src)[i];
        __half2* d = reinterpret_cast<__half2*>(dst) + 2 * i;
        d[0] = __floats2half2_rn(v.x, v.y);
        d[1] = __floats2half2_rn(v.z, v.w);
    }
}

__global__ __launch_bounds__(256) void prep_kernel(
    const float* __restrict__ feats, const float* __restrict__ boxes,
    const float* __restrict__ W1, const float* __restrict__ W2,
    const float* __restrict__ Wc, const float* __restrict__ bc,
    const float* __restrict__ Wr, const float* __restrict__ br)
{
    unsigned b = blockIdx.x;
    if (b >= NBOX) {
        unsigned r = b - NBOX;
        if (r < W1B) { convert_body(W1, g_w1h, W1N4, r); return; }
        r -= W1B;
        if (r < W2B) { convert_body(W2, g_w2h, W2N4, r); return; }
        r -= W2B;
        if (r < WCRB) {                       // pack head weights
            size_t i = (size_t)r * 256 + threadIdx.x;
            if (i < WCRN) {
                int c = (int)(i & (NHC - 1));
                size_t k = i >> 7;
                float v = 0.f;
                if (c < NCLS)      v = Wc[k * NCLS + c];
                else if (c < NOUT) v = Wr[k * NREG + (c - NCLS)];
                g_wcrh[i] = __float2half_rn(v);
            }
            return;
        }
        // bias pack (single block)
        int t = threadIdx.x;
        if (t < NHC) {
            float v = 0.f;
            if (t < NCLS)      v = bc[t];
            else if (t < NOUT) v = br[t - NCLS];
            g_bcr[t] = v;
        }
        return;
    }
    // ---- roi_pool for box n = b ----
    int n = b;
    __shared__ int   sy0[CROP], sy1[CROP], sx0[CROP], sx1[CROP];
    __shared__ float swy[CROP], swx[CROP];

    int t = threadIdx.x;
    if (t < 2 * CROP) {
        int  i   = t % CROP;
        bool isY = (t < CROP);
        float b1 = boxes[n * 4 + (isY ? 0 : 1)];
        float b2 = boxes[n * 4 + (isY ? 2 : 3)];
        float S  = isY ? (float)(FH - 1) : (float)(FW - 1);
        int   lim = isY ? (FH - 1) : (FW - 1);
        float v  = b1 * S + (float)i * ((b2 - b1) * S / (float)(CROP - 1));
        float f  = floorf(v);
        int i0 = (int)f;
        i0 = min(max(i0, 0), lim);
        int i1 = min(i0 + 1, lim);
        float w = v - f;
        if (isY) { sy0[i] = i0; sy1[i] = i1; swy[i] = w; }
        else     { sx0[i] = i0; sx1[i] = i1; swx[i] = w; }
    }
    __syncthreads();

    const float4* F4 = reinterpret_cast<const float4*>(feats);
    __half2* H2 = reinterpret_cast<__half2*>(g_pooledh);

    for (int idx = t; idx < RS * RS * FC4; idx += 256) {
        int c4 = idx & (FC4 - 1);
        int p  = idx >> 7;
        int px = p % RS;
        int py = p / RS;

        float4 best = make_float4(-3.4e38f, -3.4e38f, -3.4e38f, -3.4e38f);
        #pragma unroll
        for (int dy = 0; dy < 2; dy++) {
            int iy = 2 * py + dy;
            int y0 = sy0[iy], y1 = sy1[iy];
            float wy = swy[iy], omwy = 1.f - wy;
            #pragma unroll
            for (int dx = 0; dx < 2; dx++) {
                int ix = 2 * px + dx;
                int x0 = sx0[ix], x1 = sx1[ix];
                float wx = swx[ix], omwx = 1.f - wx;
                float4 a = F4[(y0 * FW + x0) * FC4 + c4];
                float4 bb = F4[(y0 * FW + x1) * FC4 + c4];
                float4 c = F4[(y1 * FW + x0) * FC4 + c4];
                float4 d = F4[(y1 * FW + x1) * FC4 + c4];
                float4 v;
                v.x = (a.x * omwx + bb.x * wx) * omwy + (c.x * omwx + d.x * wx) * wy;
                v.y = (a.y * omwx + bb.y * wx) * omwy + (c.y * omwx + d.y * wx) * wy;
                v.z = (a.z * omwx + bb.z * wx) * omwy + (c.z * omwx + d.z * wx) * wy;
                v.w = (a.w * omwx + bb.w * wx) * omwy + (c.w * omwx + d.w * wx) * wy;
                best.x = fmaxf(best.x, v.x);
                best.y = fmaxf(best.y, v.y);
                best.z = fmaxf(best.z, v.z);
                best.w = fmaxf(best.w, v.w);
            }
        }
        size_t base = (size_t)n * DFLAT + (size_t)p * FC + c4 * 4;
        H2[base / 2]     = __floats2half2_rn(best.x, best.y);
        H2[base / 2 + 1] = __floats2half2_rn(best.z, best.w);
    }
}

// ===================== Kernel 2: fp16 wmma GEMM + bias (+relu) ==============
#define GNS 4
#define BM 128
#define BN 128
#define BK 32
#define APAD 8
#define BPAD 8
#define AS_STRIDE (BK + APAD)                 // 40 halves
#define BS_STRIDE (BN + BPAD)                 // 136 halves
#define A_TILE_BYTES (BM * AS_STRIDE * 2)     // 10240
#define B_TILE_BYTES (BK * BS_STRIDE * 2)     // 8704
#define STAGE_BYTES  (A_TILE_BYTES + B_TILE_BYTES)   // 18944
#define GEMM_DSMEM   (GNS * STAGE_BYTES)      // 75776

__global__ __launch_bounds__(256, 2) void gemm_fp16_kernel(
    const __half* __restrict__ A, const __half* __restrict__ B,
    const float* __restrict__ bias, void* __restrict__ Cv,
    int M, int N, int K, int half_out, int do_relu)
{
    extern __shared__ char dsm[];
    int tid = threadIdx.x, warpId = tid >> 5, lane = tid & 31;
    int m0 = blockIdx.y * BM, n0 = blockIdx.x * BN;
    int wm = warpId & 1;      // 2 M-groups of 64
    int wn = warpId >> 1;     // 4 N-groups of 32
    const int KT = K / BK;

    wmma::fragment<wmma::accumulator, 16, 16, 16, float> acc[4][2];
    #pragma unroll
    for (int i = 0; i < 4; i++)
        #pragma unroll
        for (int j = 0; j < 2; j++)
            wmma::fill_fragment(acc[i][j], 0.0f);

    auto load_tile = [&](int j) {
        char* st = dsm + (j & (GNS - 1)) * STAGE_BYTES;
        uint32_t sA = smem_u32(st);
        uint32_t sB = sA + A_TILE_BYTES;
        int kb = j * BK;
        #pragma unroll
        for (int i = 0; i < 2; i++) {
            int idx = i * 256 + tid;
            int row = idx >> 2, c = idx & 3;
            int gm = m0 + row;
            const __half* src = A + (size_t)min(gm, M - 1) * K + kb + c * 8;
            cp_async16(sA + row * (AS_STRIDE * 2) + c * 16, src, (gm < M) ? 16 : 0);
        }
        #pragma unroll
        for (int i = 0; i < 2; i++) {
            int idx = i * 256 + tid;
            int row = idx >> 4, c = idx & 15;
            const __half* src = B + (size_t)(kb + row) * N + n0 + c * 8;
            cp_async16(sB + row * (BS_STRIDE * 2) + c * 16, src, 16);
        }
        CP_COMMIT();
    };

    for (int j = 0; j < GNS - 1; j++) load_tile(j);

    for (int it = 0; it < KT; it++) {
        CP_WAIT(GNS - 2);
        __syncthreads();

        int j = it + GNS - 1;
        if (j < KT) load_tile(j);
        else        CP_COMMIT();   // keep wait_group counting exact in the tail

        const char* st = dsm + (it & (GNS - 1)) * STAGE_BYTES;
        const __half* sA = reinterpret_cast<const __half*>(st);
        const __half* sB = reinterpret_cast<const __half*>(st + A_TILE_BYTES);

        #pragma unroll
        for (int kk = 0; kk < BK; kk += 16) {
            wmma::fragment<wmma::matrix_a, 16, 16, 16, __half, wmma::row_major> af[4];
            wmma::fragment<wmma::matrix_b, 16, 16, 16, __half, wmma::row_major> bf[2];
            #pragma unroll
            for (int i = 0; i < 4; i++)
                wmma::load_matrix_sync(af[i], sA + (wm * 64 + i * 16) * AS_STRIDE + kk, AS_STRIDE);
            #pragma unroll
            for (int j2 = 0; j2 < 2; j2++)
                wmma::load_matrix_sync(bf[j2], sB + kk * BS_STRIDE + wn * 32 + j2 * 16, BS_STRIDE);
            #pragma unroll
            for (int i = 0; i < 4; i++)
                #pragma unroll
                for (int j2 = 0; j2 < 2; j2++)
                    wmma::mma_sync(acc[i][j2], af[i], bf[j2], acc[i][j2]);
        }
    }

    __syncthreads();
    float* stg = reinterpret_cast<float*>(dsm) + warpId * 16 * 20;
    #pragma unroll
    for (int i = 0; i < 4; i++) {
        #pragma unroll
        for (int j2 = 0; j2 < 2; j2++) {
            wmma::store_matrix_sync(stg, acc[i][j2], 20, wmma::mem_row_major);
            __syncwarp();
            #pragma unroll
            for (int e = lane; e < 256; e += 32) {
                int r = e >> 4, cc = e & 15;
                int gm = m0 + wm * 64 + i * 16 + r;
                int gn = n0 + wn * 32 + j2 * 16 + cc;
                if (gm < M) {
                    float v = stg[r * 20 + cc] + bias[gn];
                    if (do_relu) v = fmaxf(v, 0.0f);
                    if (half_out)
                        reinterpret_cast<__half*>(Cv)[(size_t)gm * N + gn] = __float2half_rn(v);
                    else
                        reinterpret_cast<float*>(Cv)[(size_t)gm * N + gn] = v;
                }
            }
            __syncwarp();
        }
    }
}

// ===================== Kernel 3: softmax + scatter ==========================
// grid NBOX/8, 8 warps/block, warp w -> box. g_logits already has bias added.
__global__ __launch_bounds__(256) void heads_final_kernel(float* __restrict__ out)
{
    int n = blockIdx.x * 8 + (threadIdx.x >> 5);
    int lane = threadIdx.x & 31;
    const float* row = g_logits + (size_t)n * NHC;

    float v[4];
    #pragma unroll
    for (int j = 0; j < 4; j++) v[j] = row[j * 32 + lane];

    // reg outputs: columns 21..100
    #pragma unroll
    for (int j = 0; j < 4; j++) {
        int cc = j * 32 + lane;
        if (cc >= NCLS && cc < NOUT)
            out[(size_t)NBOX * NCLS + (size_t)n * NREG + (cc - NCLS)] = v[j];
    }
    // softmax over columns 0..20
    float cv = (lane < NCLS) ? v[0] : -3.4e38f;
    float m = cv;
    #pragma unroll
    for (int o = 16; o; o >>= 1) m = fmaxf(m, __shfl_xor_sync(0xffffffff, m, o));
    float e = (lane < NCLS) ? expf(cv - m) : 0.f;
    float ssum = e;
    #pragma unroll
    for (int o = 16; o; o >>= 1) ssum += __shfl_xor_sync(0xffffffff, ssum, o);
    if (lane < NCLS)
        out[(size_t)n * NCLS + lane] = e / ssum;
}

// ===================== launcher ============================================
extern "C" void kernel_launch(void* const* d_in, const int* in_sizes, int n_in,
                              void* d_out, int out_size)
{
    const float* feats = (const float*)d_in[0];
    const float* boxes = (const float*)d_in[1];
    const float* W1    = (const float*)d_in[2];
    const float* b1    = (const float*)d_in[3];
    const float* W2    = (const float*)d_in[4];
    const float* b2    = (const float*)d_in[5];
    const float* Wc    = (const float*)d_in[6];
    const float* bc    = (const float*)d_in[7];
    const float* Wr    = (const float*)d_in[8];
    const float* br    = (const float*)d_in[9];
    float* out = (float*)d_out;

    __half* w1h;  cudaGetSymbolAddress((void**)&w1h,  g_w1h);
    __half* w2h;  cudaGetSymbolAddress((void**)&w2h,  g_w2h);
    __half* ph;   cudaGetSymbolAddress((void**)&ph,   g_pooledh);
    __half* x1h;  cudaGetSymbolAddress((void**)&x1h,  g_x1h);
    __half* x2h;  cudaGetSymbolAddress((void**)&x2h,  g_x2h);
    __half* wcrh; cudaGetSymbolAddress((void**)&wcrh, g_wcrh);
    float*  bcr;  cudaGetSymbolAddress((void**)&bcr,  g_bcr);
    float*  lg;   cudaGetSymbolAddress((void**)&lg,   g_logits);

    cudaFuncSetAttribute(gemm_fp16_kernel,
                         cudaFuncAttributeMaxDynamicSharedMemorySize, GEMM_DSMEM);

    prep_kernel<<<NBOX + W1B + W2B + WCRB + 1, 256>>>(feats, boxes, W1, W2, Wc, bc, Wr, br);

    dim3 g1(D1 / BN, (NBOX + BM - 1) / BM);   // (32, 8)
    gemm_fp16_kernel<<<g1, 256, GEMM_DSMEM>>>(ph,  w1h, b1, x1h, NBOX, D1, DFLAT, 1, 1);
    gemm_fp16_kernel<<<g1, 256, GEMM_DSMEM>>>(x1h, w2h, b2, x2h, NBOX, D1, D1,    1, 1);

    // GEMM3: heads logits = x2h @ [Wc|Wr] + [bc|br]  (no relu, fp32 out)
    dim3 g3(NHC / BN, (NBOX + BM - 1) / BM);  // (1, 8)
    gemm_fp16_kernel<<<g3, 256, GEMM_DSMEM>>>(x2h, wcrh, bcr, lg, NBOX, NHC, D1, 0, 0);

    heads_final_kernel<<<NBOX / 8, 256>>>(out);
}

// round 12
// speedup vs baseline: 1.4430x; 1.0746x over previous
#include <cuda_runtime.h>
#include <cuda_fp16.h>
#include <mma.h>
#include <math.h>
#include <stdint.h>

using namespace nvcuda;

// ---------------- problem constants ----------------
#define NBOX   1000
#define FH     38
#define FW     50
#define FC     512
#define FC4    128
#define CROP   14
#define RS     7
#define DFLAT  25088        // 7*7*512
#define D1     4096
#define NCLS   21
#define NREG   80
#define NOUT   101          // NCLS + NREG
#define NHC    128          // padded head cols
#define HKS    16           // heads split-K factor (K chunk = 256)

// ---------------- scratch (device globals; no allocations allowed) ----------
__device__ __half g_pooledh[(size_t)NBOX * DFLAT];  // 50 MB
__device__ __half g_w1h[(size_t)DFLAT * D1];        // 205 MB
__device__ __half g_w2h[(size_t)D1 * D1];           // 33.5 MB
__device__ __half g_x1h[(size_t)NBOX * D1];
__device__ __half g_x2h[(size_t)NBOX * D1];         // fp16 heads input
__device__ __half g_wcrh[(size_t)D1 * NHC];         // packed [Wc|Wr|0] fp16, 1 MB
__device__ float  g_bcr[NHC];                       // packed [bc|br|0]
__device__ float  g_hpart[HKS][(size_t)NBOX * NHC]; // split-K partials, 8.2 MB

// ---------------- helpers ----------------
__device__ __forceinline__ uint32_t smem_u32(const void* p) {
    uint32_t a;
    asm("{ .reg .u64 t; cvta.to.shared.u64 t, %1; cvt.u32.u64 %0, t; }" : "=r"(a) : "l"(p));
    return a;
}
__device__ __forceinline__ void cp_async16(uint32_t dst, const void* src, int sz) {
    asm volatile("cp.async.cg.shared.global [%0], [%1], 16, %2;" :: "r"(dst), "l"(src), "r"(sz));
}
#define CP_COMMIT() asm volatile("cp.async.commit_group;" ::: "memory")
#define CP_WAIT(n)  asm volatile("cp.async.wait_group %0;" :: "n"(n) : "memory")

// ===================== Kernel 1: fused prep =================================
#define W1N4 (((size_t)DFLAT * D1) / 4)
#define W2N4 (((size_t)D1 * D1) / 4)
#define W1B  ((unsigned)((W1N4 + 255) / 256))
#define W2B  ((unsigned)((W2N4 + 255) / 256))
#define WCRN (((size_t)D1 * NHC))
#define WCRB ((unsigned)((WCRN + 255) / 256))

__device__ __forceinline__ void convert_body(const float* __restrict__ src,
                                             __half* __restrict__ dst,
                                             size_t n4, unsigned blk)
{
    size_t i = (size_t)blk * 256 + threadIdx.x;
    if (i < n4) {
        float4 v = reinterpret_cast<const float4*>(src)[i];
        __half2* d = reinterpret_cast<__half2*>(dst) + 2 * i;
        d[0] = __floats2half2_rn(v.x, v.y);
        d[1] = __floats2half2_rn(v.z, v.w);
    }
}

__global__ __launch_bounds__(256) void prep_kernel(
    const float* __restrict__ feats, const float* __restrict__ boxes,
    const float* __restrict__ W1, const float* __restrict__ W2,
    const float* __restrict__ Wc, const float* __restrict__ bc,
    const float* __restrict__ Wr, const float* __restrict__ br)
{
    unsigned b = blockIdx.x;
    if (b >= NBOX) {
        unsigned r = b - NBOX;
        if (r < W1B) { convert_body(W1, g_w1h, W1N4, r); return; }
        r -= W1B;
        if (r < W2B) { convert_body(W2, g_w2h, W2N4, r); return; }
        r -= W2B;
        if (r < WCRB) {                       // pack head weights
            size_t i = (size_t)r * 256 + threadIdx.x;
            if (i < WCRN) {
                int c = (int)(i & (NHC - 1));
                size_t k = i >> 7;
                float v = 0.f;
                if (c < NCLS)      v = Wc[k * NCLS + c];
                else if (c < NOUT) v = Wr[k * NREG + (c - NCLS)];
                g_wcrh[i] = __float2half_rn(v);
            }
            return;
        }
        int t = threadIdx.x;                  // bias pack
        if (t < NHC) {
            float v = 0.f;
            if (t < NCLS)      v = bc[t];
            else if (t < NOUT) v = br[t - NCLS];
            g_bcr[t] = v;
        }
        return;
    }
    // ---- roi_pool for box n = b ----
    int n = b;
    __shared__ int   sy0[CROP], sy1[CROP], sx0[CROP], sx1[CROP];
    __shared__ float swy[CROP], swx[CROP];

    int t = threadIdx.x;
    if (t < 2 * CROP) {
        int  i   = t % CROP;
        bool isY = (t < CROP);
        float b1 = boxes[n * 4 + (isY ? 0 : 1)];
        float b2 = boxes[n * 4 + (isY ? 2 : 3)];
        float S  = isY ? (float)(FH - 1) : (float)(FW - 1);
        int   lim = isY ? (FH - 1) : (FW - 1);
        float v  = b1 * S + (float)i * ((b2 - b1) * S / (float)(CROP - 1));
        float f  = floorf(v);
        int i0 = (int)f;
        i0 = min(max(i0, 0), lim);
        int i1 = min(i0 + 1, lim);
        float w = v - f;
        if (isY) { sy0[i] = i0; sy1[i] = i1; swy[i] = w; }
        else     { sx0[i] = i0; sx1[i] = i1; swx[i] = w; }
    }
    __syncthreads();

    const float4* F4 = reinterpret_cast<const float4*>(feats);
    __half2* H2 = reinterpret_cast<__half2*>(g_pooledh);

    for (int idx = t; idx < RS * RS * FC4; idx += 256) {
        int c4 = idx & (FC4 - 1);
        int p  = idx >> 7;
        int px = p % RS;
        int py = p / RS;

        float4 best = make_float4(-3.4e38f, -3.4e38f, -3.4e38f, -3.4e38f);
        #pragma unroll
        for (int dy = 0; dy < 2; dy++) {
            int iy = 2 * py + dy;
            int y0 = sy0[iy], y1 = sy1[iy];
            float wy = swy[iy], omwy = 1.f - wy;
            #pragma unroll
            for (int dx = 0; dx < 2; dx++) {
                int ix = 2 * px + dx;
                int x0 = sx0[ix], x1 = sx1[ix];
                float wx = swx[ix], omwx = 1.f - wx;
                float4 a = F4[(y0 * FW + x0) * FC4 + c4];
                float4 bb = F4[(y0 * FW + x1) * FC4 + c4];
                float4 c = F4[(y1 * FW + x0) * FC4 + c4];
                float4 d = F4[(y1 * FW + x1) * FC4 + c4];
                float4 v;
                v.x = (a.x * omwx + bb.x * wx) * omwy + (c.x * omwx + d.x * wx) * wy;
                v.y = (a.y * omwx + bb.y * wx) * omwy + (c.y * omwx + d.y * wx) * wy;
                v.z = (a.z * omwx + bb.z * wx) * omwy + (c.z * omwx + d.z * wx) * wy;
                v.w = (a.w * omwx + bb.w * wx) * omwy + (c.w * omwx + d.w * wx) * wy;
                best.x = fmaxf(best.x, v.x);
                best.y = fmaxf(best.y, v.y);
                best.z = fmaxf(best.z, v.z);
                best.w = fmaxf(best.w, v.w);
            }
        }
        size_t base = (size_t)n * DFLAT + (size_t)p * FC + c4 * 4;
        H2[base / 2]     = __floats2half2_rn(best.x, best.y);
        H2[base / 2 + 1] = __floats2half2_rn(best.z, best.w);
    }
}

// ===================== Kernel 2: fp16 wmma GEMM + bias (+relu) ==============
#define GNS 4
#define BM 128
#define BN 128
#define BK 32
#define APAD 8
#define BPAD 8
#define AS_STRIDE (BK + APAD)                 // 40 halves
#define BS_STRIDE (BN + BPAD)                 // 136 halves
#define A_TILE_BYTES (BM * AS_STRIDE * 2)     // 10240
#define B_TILE_BYTES (BK * BS_STRIDE * 2)     // 8704
#define STAGE_BYTES  (A_TILE_BYTES + B_TILE_BYTES)   // 18944
#define GEMM_DSMEM   (GNS * STAGE_BYTES)      // 75776

__global__ __launch_bounds__(256, 2) void gemm_fp16_kernel(
    const __half* __restrict__ A, const __half* __restrict__ B,
    const float* __restrict__ bias, void* __restrict__ Cv,
    int M, int N, int K, int half_out, int do_relu)
{
    extern __shared__ char dsm[];
    int tid = threadIdx.x, warpId = tid >> 5, lane = tid & 31;
    int m0 = blockIdx.y * BM, n0 = blockIdx.x * BN;
    int wm = warpId & 1;
    int wn = warpId >> 1;
    const int KT = K / BK;

    wmma::fragment<wmma::accumulator, 16, 16, 16, float> acc[4][2];
    #pragma unroll
    for (int i = 0; i < 4; i++)
        #pragma unroll
        for (int j = 0; j < 2; j++)
            wmma::fill_fragment(acc[i][j], 0.0f);

    auto load_tile = [&](int j) {
        char* st = dsm + (j & (GNS - 1)) * STAGE_BYTES;
        uint32_t sA = smem_u32(st);
        uint32_t sB = sA + A_TILE_BYTES;
        int kb = j * BK;
        #pragma unroll
        for (int i = 0; i < 2; i++) {
            int idx = i * 256 + tid;
            int row = idx >> 2, c = idx & 3;
            int gm = m0 + row;
            const __half* src = A + (size_t)min(gm, M - 1) * K + kb + c * 8;
            cp_async16(sA + row * (AS_STRIDE * 2) + c * 16, src, (gm < M) ? 16 : 0);
        }
        #pragma unroll
        for (int i = 0; i < 2; i++) {
            int idx = i * 256 + tid;
            int row = idx >> 4, c = idx & 15;
            const __half* src = B + (size_t)(kb + row) * N + n0 + c * 8;
            cp_async16(sB + row * (BS_STRIDE * 2) + c * 16, src, 16);
        }
        CP_COMMIT();
    };

    for (int j = 0; j < GNS - 1; j++) load_tile(j);

    for (int it = 0; it < KT; it++) {
        CP_WAIT(GNS - 2);
        __syncthreads();

        int j = it + GNS - 1;
        if (j < KT) load_tile(j);
        else        CP_COMMIT();

        const char* st = dsm + (it & (GNS - 1)) * STAGE_BYTES;
        const __half* sA = reinterpret_cast<const __half*>(st);
        const __half* sB = reinterpret_cast<const __half*>(st + A_TILE_BYTES);

        #pragma unroll
        for (int kk = 0; kk < BK; kk += 16) {
            wmma::fragment<wmma::matrix_a, 16, 16, 16, __half, wmma::row_major> af[4];
            wmma::fragment<wmma::matrix_b, 16, 16, 16, __half, wmma::row_major> bf[2];
            #pragma unroll
            for (int i = 0; i < 4; i++)
                wmma::load_matrix_sync(af[i], sA + (wm * 64 + i * 16) * AS_STRIDE + kk, AS_STRIDE);
            #pragma unroll
            for (int j2 = 0; j2 < 2; j2++)
                wmma::load_matrix_sync(bf[j2], sB + kk * BS_STRIDE + wn * 32 + j2 * 16, BS_STRIDE);
            #pragma unroll
            for (int i = 0; i < 4; i++)
                #pragma unroll
                for (int j2 = 0; j2 < 2; j2++)
                    wmma::mma_sync(acc[i][j2], af[i], bf[j2], acc[i][j2]);
        }
    }

    __syncthreads();
    float* stg = reinterpret_cast<float*>(dsm) + warpId * 16 * 20;
    #pragma unroll
    for (int i = 0; i < 4; i++) {
        #pragma unroll
        for (int j2 = 0; j2 < 2; j2++) {
            wmma::store_matrix_sync(stg, acc[i][j2], 20, wmma::mem_row_major);
            __syncwarp();
            #pragma unroll
            for (int e = lane; e < 256; e += 32) {
                int r = e >> 4, cc = e & 15;
                int gm = m0 + wm * 64 + i * 16 + r;
                int gn = n0 + wn * 32 + j2 * 16 + cc;
                if (gm < M) {
                    float v = stg[r * 20 + cc] + bias[gn];
                    if (do_relu) v = fmaxf(v, 0.0f);
                    if (half_out)
                        reinterpret_cast<__half*>(Cv)[(size_t)gm * N + gn] = __float2half_rn(v);
                    else
                        reinterpret_cast<float*>(Cv)[(size_t)gm * N + gn] = v;
                }
            }
            __syncwarp();
        }
    }
}

// ===================== Kernel 3: heads split-K GEMM (tensor cores) ==========
// grid (HKS, 8). Block (ks, my): partial[ks][m0..m0+127][0..127] over K chunk 256.
__global__ __launch_bounds__(256, 2) void gemm_heads_splitk_kernel()
{
    extern __shared__ char dsm[];
    const __half* A = g_x2h;
    const __half* B = g_wcrh;
    int tid = threadIdx.x, warpId = tid >> 5, lane = tid & 31;
    int ks = blockIdx.x;
    int m0 = blockIdx.y * BM;
    int kbase = ks * (D1 / HKS);              // 256-wide K chunk
    int wm = warpId & 1;
    int wn = warpId >> 1;
    const int KT = (D1 / HKS) / BK;           // 8

    wmma::fragment<wmma::accumulator, 16, 16, 16, float> acc[4][2];
    #pragma unroll
    for (int i = 0; i < 4; i++)
        #pragma unroll
        for (int j = 0; j < 2; j++)
            wmma::fill_fragment(acc[i][j], 0.0f);

    auto load_tile = [&](int j) {
        char* st = dsm + (j & (GNS - 1)) * STAGE_BYTES;
        uint32_t sA = smem_u32(st);
        uint32_t sB = sA + A_TILE_BYTES;
        int kb = kbase + j * BK;
        #pragma unroll
        for (int i = 0; i < 2; i++) {
            int idx = i * 256 + tid;
            int row = idx >> 2, c = idx & 3;
            int gm = m0 + row;
            const __half* src = A + (size_t)min(gm, NBOX - 1) * D1 + kb + c * 8;
            cp_async16(sA + row * (AS_STRIDE * 2) + c * 16, src, (gm < NBOX) ? 16 : 0);
        }
        #pragma unroll
        for (int i = 0; i < 2; i++) {
            int idx = i * 256 + tid;
            int row = idx >> 4, c = idx & 15;
            const __half* src = B + (size_t)(kb + row) * NHC + c * 8;
            cp_async16(sB + row * (BS_STRIDE * 2) + c * 16, src, 16);
        }
        CP_COMMIT();
    };

    for (int j = 0; j < GNS - 1; j++) load_tile(j);

    for (int it = 0; it < KT; it++) {
        CP_WAIT(GNS - 2);
        __syncthreads();

        int j = it + GNS - 1;
        if (j < KT) load_tile(j);
        else        CP_COMMIT();

        const char* st = dsm + (it & (GNS - 1)) * STAGE_BYTES;
        const __half* sA = reinterpret_cast<const __half*>(st);
        const __half* sB = reinterpret_cast<const __half*>(st + A_TILE_BYTES);

        #pragma unroll
        for (int kk = 0; kk < BK; kk += 16) {
            wmma::fragment<wmma::matrix_a, 16, 16, 16, __half, wmma::row_major> af[4];
            wmma::fragment<wmma::matrix_b, 16, 16, 16, __half, wmma::row_major> bf[2];
            #pragma unroll
            for (int i = 0; i < 4; i++)
                wmma::load_matrix_sync(af[i], sA + (wm * 64 + i * 16) * AS_STRIDE + kk, AS_STRIDE);
            #pragma unroll
            for (int j2 = 0; j2 < 2; j2++)
                wmma::load_matrix_sync(bf[j2], sB + kk * BS_STRIDE + wn * 32 + j2 * 16, BS_STRIDE);
            #pragma unroll
            for (int i = 0; i < 4; i++)
                #pragma unroll
                for (int j2 = 0; j2 < 2; j2++)
                    wmma::mma_sync(acc[i][j2], af[i], bf[j2], acc[i][j2]);
        }
    }

    __syncthreads();
    float* stg = reinterpret_cast<float*>(dsm) + warpId * 16 * 20;
    float* P = &g_hpart[ks][0];
    #pragma unroll
    for (int i = 0; i < 4; i++) {
        #pragma unroll
        for (int j2 = 0; j2 < 2; j2++) {
            wmma::store_matrix_sync(stg, acc[i][j2], 20, wmma::mem_row_major);
            __syncwarp();
            #pragma unroll
            for (int e = lane; e < 256; e += 32) {
                int r = e >> 4, cc = e & 15;
                int gm = m0 + wm * 64 + i * 16 + r;
                int gn = wn * 32 + j2 * 16 + cc;
                if (gm < NBOX)
                    P[(size_t)gm * NHC + gn] = stg[r * 20 + cc];
            }
            __syncwarp();
        }
    }
}

// ===================== Kernel 4: reduce + softmax + scatter =================
// grid NBOX/8, 8 warps/block, warp -> box.
__global__ __launch_bounds__(256) void heads_final_kernel(float* __restrict__ out)
{
    int n = blockIdx.x * 8 + (threadIdx.x >> 5);
    int lane = threadIdx.x & 31;

    float v[4];
    #pragma unroll
    for (int j = 0; j < 4; j++) {
        int cc = j * 32 + lane;
        float s = g_bcr[cc];
        #pragma unroll
        for (int ks = 0; ks < HKS; ks++)
            s += g_hpart[ks][(size_t)n * NHC + cc];
        v[j] = s;
    }
    // reg outputs: columns 21..100
    #pragma unroll
    for (int j = 0; j < 4; j++) {
        int cc = j * 32 + lane;
        if (cc >= NCLS && cc < NOUT)
            out[(size_t)NBOX * NCLS + (size_t)n * NREG + (cc - NCLS)] = v[j];
    }
    // softmax over columns 0..20
    float cv = (lane < NCLS) ? v[0] : -3.4e38f;
    float m = cv;
    #pragma unroll
    for (int o = 16; o; o >>= 1) m = fmaxf(m, __shfl_xor_sync(0xffffffff, m, o));
    float e = (lane < NCLS) ? expf(cv - m) : 0.f;
    float ssum = e;
    #pragma unroll
    for (int o = 16; o; o >>= 1) ssum += __shfl_xor_sync(0xffffffff, ssum, o);
    if (lane < NCLS)
        out[(size_t)n * NCLS + lane] = e / ssum;
}

// ===================== launcher ============================================
extern "C" void kernel_launch(void* const* d_in, const int* in_sizes, int n_in,
                              void* d_out, int out_size)
{
    const float* feats = (const float*)d_in[0];
    const float* boxes = (const float*)d_in[1];
    const float* W1    = (const float*)d_in[2];
    const float* b1    = (const float*)d_in[3];
    const float* W2    = (const float*)d_in[4];
    const float* b2    = (const float*)d_in[5];
    const float* Wc    = (const float*)d_in[6];
    const float* bc    = (const float*)d_in[7];
    const float* Wr    = (const float*)d_in[8];
    const float* br    = (const float*)d_in[9];
    float* out = (float*)d_out;

    __half* w1h;  cudaGetSymbolAddress((void**)&w1h,  g_w1h);
    __half* w2h;  cudaGetSymbolAddress((void**)&w2h,  g_w2h);
    __half* ph;   cudaGetSymbolAddress((void**)&ph,   g_pooledh);
    __half* x1h;  cudaGetSymbolAddress((void**)&x1h,  g_x1h);
    __half* x2h;  cudaGetSymbolAddress((void**)&x2h,  g_x2h);

    cudaFuncSetAttribute(gemm_fp16_kernel,
                         cudaFuncAttributeMaxDynamicSharedMemorySize, GEMM_DSMEM);
    cudaFuncSetAttribute(gemm_heads_splitk_kernel,
                         cudaFuncAttributeMaxDynamicSharedMemorySize, GEMM_DSMEM);

    prep_kernel<<<NBOX + W1B + W2B + WCRB + 1, 256>>>(feats, boxes, W1, W2, Wc, bc, Wr, br);

    dim3 g1(D1 / BN, (NBOX + BM - 1) / BM);   // (32, 8)
    gemm_fp16_kernel<<<g1, 256, GEMM_DSMEM>>>(ph,  w1h, b1, x1h, NBOX, D1, DFLAT, 1, 1);
    gemm_fp16_kernel<<<g1, 256, GEMM_DSMEM>>>(x1h, w2h, b2, x2h, NBOX, D1, D1,    1, 1);

    gemm_heads_splitk_kernel<<<dim3(HKS, (NBOX + BM - 1) / BM), 256, GEMM_DSMEM>>>();
    heads_final_kernel<<<NBOX / 8, 256>>>(out);
}

// round 14
// speedup vs baseline: 1.5706x; 1.0884x over previous
#include <cuda_runtime.h>
#include <cuda_fp16.h>
#include <mma.h>
#include <math.h>
#include <stdint.h>

using namespace nvcuda;

// ---------------- problem constants ----------------
#define NBOX   1000
#define FH     38
#define FW     50
#define FC     512
#define FC4    128
#define CROP   14
#define RS     7
#define DFLAT  25088        // 7*7*512
#define D1     4096
#define NCLS   21
#define NREG   80
#define NOUT   101          // NCLS + NREG
#define NHC    128          // padded head cols
#define HKS    16           // heads split-K factor (K chunk = 256)

// ---------------- scratch (device globals; no allocations allowed) ----------
__device__ __half g_pooledh[(size_t)NBOX * DFLAT];  // 50 MB
__device__ __half g_w1h[(size_t)DFLAT * D1];        // 205 MB
__device__ __half g_w2h[(size_t)D1 * D1];           // 33.5 MB
__device__ __half g_x1h[(size_t)NBOX * D1];
__device__ __half g_x2h[(size_t)NBOX * D1];         // fp16 heads input
__device__ __half g_wcrh[(size_t)D1 * NHC];         // packed [Wc|Wr|0] fp16, 1 MB
__device__ float  g_bcr[NHC];                       // packed [bc|br|0]
__device__ float  g_hpart[HKS][(size_t)NBOX * NHC]; // split-K partials, 8.2 MB

// ---------------- helpers ----------------
__device__ __forceinline__ uint32_t smem_u32(const void* p) {
    uint32_t a;
    asm("{ .reg .u64 t; cvta.to.shared.u64 t, %1; cvt.u32.u64 %0, t; }" : "=r"(a) : "l"(p));
    return a;
}
__device__ __forceinline__ void cp_async16(uint32_t dst, const void* src, int sz) {
    asm volatile("cp.async.cg.shared.global [%0], [%1], 16, %2;" :: "r"(dst), "l"(src), "r"(sz));
}
#define CP_COMMIT() asm volatile("cp.async.commit_group;" ::: "memory")
#define CP_WAIT(n)  asm volatile("cp.async.wait_group %0;" :: "n"(n) : "memory")

// ===================== Kernel 1: fused prep =================================
#define W1N4 (((size_t)DFLAT * D1) / 4)
#define W2N4 (((size_t)D1 * D1) / 4)
#define W1B  ((unsigned)((W1N4 + 255) / 256))
#define W2B  ((unsigned)((W2N4 + 255) / 256))
#define WCRN (((size_t)D1 * NHC))
#define WCRB ((unsigned)((WCRN + 255) / 256))

__device__ __forceinline__ void convert_body(const float* __restrict__ src,
                                             __half* __restrict__ dst,
                                             size_t n4, unsigned blk)
{
    size_t i = (size_t)blk * 256 + threadIdx.x;
    if (i < n4) {
        float4 v = reinterpret_cast<const float4*>(src)[i];
        __half2* d = reinterpret_cast<__half2*>(dst) + 2 * i;
        d[0] = __floats2half2_rn(v.x, v.y);
        d[1] = __floats2half2_rn(v.z, v.w);
    }
}

__global__ __launch_bounds__(256) void prep_kernel(
    const float* __restrict__ feats, const float* __restrict__ boxes,
    const float* __restrict__ W1, const float* __restrict__ W2,
    const float* __restrict__ Wc, const float* __restrict__ bc,
    const float* __restrict__ Wr, const float* __restrict__ br)
{
    unsigned b = blockIdx.x;
    if (b >= NBOX) {
        unsigned r = b - NBOX;
        if (r < W1B) { convert_body(W1, g_w1h, W1N4, r); return; }
        r -= W1B;
        if (r < W2B) { convert_body(W2, g_w2h, W2N4, r); return; }
        r -= W2B;
        if (r < WCRB) {                       // pack head weights
            size_t i = (size_t)r * 256 + threadIdx.x;
            if (i < WCRN) {
                int c = (int)(i & (NHC - 1));
                size_t k = i >> 7;
                float v = 0.f;
                if (c < NCLS)      v = Wc[k * NCLS + c];
                else if (c < NOUT) v = Wr[k * NREG + (c - NCLS)];
                g_wcrh[i] = __float2half_rn(v);
            }
            return;
        }
        int t = threadIdx.x;                  // bias pack
        if (t < NHC) {
            float v = 0.f;
            if (t < NCLS)      v = bc[t];
            else if (t < NOUT) v = br[t - NCLS];
            g_bcr[t] = v;
        }
        return;
    }
    // ---- roi_pool for box n = b ----
    int n = b;
    __shared__ int   sy0[CROP], sy1[CROP], sx0[CROP], sx1[CROP];
    __shared__ float swy[CROP], swx[CROP];

    int t = threadIdx.x;
    if (t < 2 * CROP) {
        int  i   = t % CROP;
        bool isY = (t < CROP);
        float b1 = boxes[n * 4 + (isY ? 0 : 1)];
        float b2 = boxes[n * 4 + (isY ? 2 : 3)];
        float S  = isY ? (float)(FH - 1) : (float)(FW - 1);
        int   lim = isY ? (FH - 1) : (FW - 1);
        float v  = b1 * S + (float)i * ((b2 - b1) * S / (float)(CROP - 1));
        float f  = floorf(v);
        int i0 = (int)f;
        i0 = min(max(i0, 0), lim);
        int i1 = min(i0 + 1, lim);
        float w = v - f;
        if (isY) { sy0[i] = i0; sy1[i] = i1; swy[i] = w; }
        else     { sx0[i] = i0; sx1[i] = i1; swx[i] = w; }
    }
    __syncthreads();

    const float4* F4 = reinterpret_cast<const float4*>(feats);
    __half2* H2 = reinterpret_cast<__half2*>(g_pooledh);

    for (int idx = t; idx < RS * RS * FC4; idx += 256) {
        int c4 = idx & (FC4 - 1);
        int p  = idx >> 7;
        int px = p % RS;
        int py = p / RS;

        float4 best = make_float4(-3.4e38f, -3.4e38f, -3.4e38f, -3.4e38f);
        #pragma unroll
        for (int dy = 0; dy < 2; dy++) {
            int iy = 2 * py + dy;
            int y0 = sy0[iy], y1 = sy1[iy];
            float wy = swy[iy], omwy = 1.f - wy;
            #pragma unroll
            for (int dx = 0; dx < 2; dx++) {
                int ix = 2 * px + dx;
                int x0 = sx0[ix], x1 = sx1[ix];
                float wx = swx[ix], omwx = 1.f - wx;
                float4 a = F4[(y0 * FW + x0) * FC4 + c4];
                float4 bb = F4[(y0 * FW + x1) * FC4 + c4];
                float4 c = F4[(y1 * FW + x0) * FC4 + c4];
                float4 d = F4[(y1 * FW + x1) * FC4 + c4];
                float4 v;
                v.x = (a.x * omwx + bb.x * wx) * omwy + (c.x * omwx + d.x * wx) * wy;
                v.y = (a.y * omwx + bb.y * wx) * omwy + (c.y * omwx + d.y * wx) * wy;
                v.z = (a.z * omwx + bb.z * wx) * omwy + (c.z * omwx + d.z * wx) * wy;
                v.w = (a.w * omwx + bb.w * wx) * omwy + (c.w * omwx + d.w * wx) * wy;
                best.x = fmaxf(best.x, v.x);
                best.y = fmaxf(best.y, v.y);
                best.z = fmaxf(best.z, v.z);
                best.w = fmaxf(best.w, v.w);
            }
        }
        size_t base = (size_t)n * DFLAT + (size_t)p * FC + c4 * 4;
        H2[base / 2]     = __floats2half2_rn(best.x, best.y);
        H2[base / 2 + 1] = __floats2half2_rn(best.z, best.w);
    }
}

// ===================== Kernel 2: fp16 wmma GEMM + bias (+relu) ==============
// 128x128x32 CTA tile, 4 warps (2M x 2N), 64x64 warp tile, 4-stage cp.async.
#define GNS 4
#define BM 128
#define BN 128
#define BK 32
#define APAD 8
#define BPAD 8
#define AS_STRIDE (BK + APAD)                 // 40 halves
#define BS_STRIDE (BN + BPAD)                 // 136 halves
#define A_TILE_BYTES (BM * AS_STRIDE * 2)     // 10240
#define B_TILE_BYTES (BK * BS_STRIDE * 2)     // 8704
#define STAGE_BYTES  (A_TILE_BYTES + B_TILE_BYTES)   // 18944
#define GEMM_DSMEM   (GNS * STAGE_BYTES)      // 75776
#define GTHREADS 128

__global__ __launch_bounds__(GTHREADS, 2) void gemm_fp16_kernel(
    const __half* __restrict__ A, const __half* __restrict__ B,
    const float* __restrict__ bias, void* __restrict__ Cv,
    int M, int N, int K, int half_out, int do_relu)
{
    extern __shared__ char dsm[];
    int tid = threadIdx.x, warpId = tid >> 5, lane = tid & 31;
    int m0 = blockIdx.y * BM, n0 = blockIdx.x * BN;
    int wm = warpId & 1;      // 2 M-groups of 64
    int wn = warpId >> 1;     // 2 N-groups of 64
    const int KT = K / BK;

    wmma::fragment<wmma::accumulator, 16, 16, 16, float> acc[4][4];
    #pragma unroll
    for (int i = 0; i < 4; i++)
        #pragma unroll
        for (int j = 0; j < 4; j++)
            wmma::fill_fragment(acc[i][j], 0.0f);

    auto load_tile = [&](int j) {
        char* st = dsm + (j & (GNS - 1)) * STAGE_BYTES;
        uint32_t sA = smem_u32(st);
        uint32_t sB = sA + A_TILE_BYTES;
        int kb = j * BK;
        // A: 512 x 16B chunks, 4 per thread
        #pragma unroll
        for (int i = 0; i < 4; i++) {
            int idx = i * GTHREADS + tid;
            int row = idx >> 2, c = idx & 3;
            int gm = m0 + row;
            const __half* src = A + (size_t)min(gm, M - 1) * K + kb + c * 8;
            cp_async16(sA + row * (AS_STRIDE * 2) + c * 16, src, (gm < M) ? 16 : 0);
        }
        // B: 512 x 16B chunks, 4 per thread
        #pragma unroll
        for (int i = 0; i < 4; i++) {
            int idx = i * GTHREADS + tid;
            int row = idx >> 4, c = idx & 15;
            const __half* src = B + (size_t)(kb + row) * N + n0 + c * 8;
            cp_async16(sB + row * (BS_STRIDE * 2) + c * 16, src, 16);
        }
        CP_COMMIT();
    };

    for (int j = 0; j < GNS - 1; j++) load_tile(j);

    for (int it = 0; it < KT; it++) {
        CP_WAIT(GNS - 2);
        __syncthreads();

        int j = it + GNS - 1;
        if (j < KT) load_tile(j);
        else        CP_COMMIT();   // keep wait_group counting exact in the tail

        const char* st = dsm + (it & (GNS - 1)) * STAGE_BYTES;
        const __half* sA = reinterpret_cast<const __half*>(st);
        const __half* sB = reinterpret_cast<const __half*>(st + A_TILE_BYTES);

        #pragma unroll
        for (int kk = 0; kk < BK; kk += 16) {
            wmma::fragment<wmma::matrix_a, 16, 16, 16, __half, wmma::row_major> af[4];
            wmma::fragment<wmma::matrix_b, 16, 16, 16, __half, wmma::row_major> bf[4];
            #pragma unroll
            for (int i = 0; i < 4; i++)
                wmma::load_matrix_sync(af[i], sA + (wm * 64 + i * 16) * AS_STRIDE + kk, AS_STRIDE);
            #pragma unroll
            for (int j2 = 0; j2 < 4; j2++)
                wmma::load_matrix_sync(bf[j2], sB + kk * BS_STRIDE + wn * 64 + j2 * 16, BS_STRIDE);
            #pragma unroll
            for (int i = 0; i < 4; i++)
                #pragma unroll
                for (int j2 = 0; j2 < 4; j2++)
                    wmma::mma_sync(acc[i][j2], af[i], bf[j2], acc[i][j2]);
        }
    }

    __syncthreads();
    float* stg = reinterpret_cast<float*>(dsm) + warpId * 16 * 20;
    #pragma unroll
    for (int i = 0; i < 4; i++) {
        #pragma unroll
        for (int j2 = 0; j2 < 4; j2++) {
            wmma::store_matrix_sync(stg, acc[i][j2], 20, wmma::mem_row_major);
            __syncwarp();
            #pragma unroll
            for (int e = lane; e < 256; e += 32) {
                int r = e >> 4, cc = e & 15;
                int gm = m0 + wm * 64 + i * 16 + r;
                int gn = n0 + wn * 64 + j2 * 16 + cc;
                if (gm < M) {
                    float v = stg[r * 20 + cc] + bias[gn];
                    if (do_relu) v = fmaxf(v, 0.0f);
                    if (half_out)
                        reinterpret_cast<__half*>(Cv)[(size_t)gm * N + gn] = __float2half_rn(v);
                    else
                        reinterpret_cast<float*>(Cv)[(size_t)gm * N + gn] = v;
                }
            }
            __syncwarp();
        }
    }
}

// ===================== Kernel 3: heads split-K GEMM (tensor cores) ==========
// grid (HKS, 8). Block (ks, my): partial[ks][m0..m0+127][0..127] over K chunk 256.
__global__ __launch_bounds__(GTHREADS, 2) void gemm_heads_splitk_kernel()
{
    extern __shared__ char dsm[];
    const __half* A = g_x2h;
    const __half* B = g_wcrh;
    int tid = threadIdx.x, warpId = tid >> 5, lane = tid & 31;
    int ks = blockIdx.x;
    int m0 = blockIdx.y * BM;
    int kbase = ks * (D1 / HKS);              // 256-wide K chunk
    int wm = warpId & 1;
    int wn = warpId >> 1;
    const int KT = (D1 / HKS) / BK;           // 8

    wmma::fragment<wmma::accumulator, 16, 16, 16, float> acc[4][4];
    #pragma unroll
    for (int i = 0; i < 4; i++)
        #pragma unroll
        for (int j = 0; j < 4; j++)
            wmma::fill_fragment(acc[i][j], 0.0f);

    auto load_tile = [&](int j) {
        char* st = dsm + (j & (GNS - 1)) * STAGE_BYTES;
        uint32_t sA = smem_u32(st);
        uint32_t sB = sA + A_TILE_BYTES;
        int kb = kbase + j * BK;
        #pragma unroll
        for (int i = 0; i < 4; i++) {
            int idx = i * GTHREADS + tid;
            int row = idx >> 2, c = idx & 3;
            int gm = m0 + row;
            const __half* src = A + (size_t)min(gm, NBOX - 1) * D1 + kb + c * 8;
            cp_async16(sA + row * (AS_STRIDE * 2) + c * 16, src, (gm < NBOX) ? 16 : 0);
        }
        #pragma unroll
        for (int i = 0; i < 4; i++) {
            int idx = i * GTHREADS + tid;
            int row = idx >> 4, c = idx & 15;
            const __half* src = B + (size_t)(kb + row) * NHC + c * 8;
            cp_async16(sB + row * (BS_STRIDE * 2) + c * 16, src, 16);
        }
        CP_COMMIT();
    };

    for (int j = 0; j < GNS - 1; j++) load_tile(j);

    for (int it = 0; it < KT; it++) {
        CP_WAIT(GNS - 2);
        __syncthreads();

        int j = it + GNS - 1;
        if (j < KT) load_tile(j);
        else        CP_COMMIT();

        const char* st = dsm + (it & (GNS - 1)) * STAGE_BYTES;
        const __half* sA = reinterpret_cast<const __half*>(st);
        const __half* sB = reinterpret_cast<const __half*>(st + A_TILE_BYTES);

        #pragma unroll
        for (int kk = 0; kk < BK; kk += 16) {
            wmma::fragment<wmma::matrix_a, 16, 16, 16, __half, wmma::row_major> af[4];
            wmma::fragment<wmma::matrix_b, 16, 16, 16, __half, wmma::row_major> bf[4];
            #pragma unroll
            for (int i = 0; i < 4; i++)
                wmma::load_matrix_sync(af[i], sA + (wm * 64 + i * 16) * AS_STRIDE + kk, AS_STRIDE);
            #pragma unroll
            for (int j2 = 0; j2 < 4; j2++)
                wmma::load_matrix_sync(bf[j2], sB + kk * BS_STRIDE + wn * 64 + j2 * 16, BS_STRIDE);
            #pragma unroll
            for (int i = 0; i < 4; i++)
                #pragma unroll
                for (int j2 = 0; j2 < 4; j2++)
                    wmma::mma_sync(acc[i][j2], af[i], bf[j2], acc[i][j2]);
        }
    }

    __syncthreads();
    float* stg = reinterpret_cast<float*>(dsm) + warpId * 16 * 20;
    float* P = &g_hpart[ks][0];
    #pragma unroll
    for (int i = 0; i < 4; i++) {
        #pragma unroll
        for (int j2 = 0; j2 < 4; j2++) {
            wmma::store_matrix_sync(stg, acc[i][j2], 20, wmma::mem_row_major);
            __syncwarp();
            #pragma unroll
            for (int e = lane; e < 256; e += 32) {
                int r = e >> 4, cc = e & 15;
                int gm = m0 + wm * 64 + i * 16 + r;
                int gn = wn * 64 + j2 * 16 + cc;
                if (gm < NBOX)
                    P[(size_t)gm * NHC + gn] = stg[r * 20 + cc];
            }
            __syncwarp();
        }
    }
}

// ===================== Kernel 4: reduce + softmax + scatter =================
__global__ __launch_bounds__(256) void heads_final_kernel(float* __restrict__ out)
{
    int n = blockIdx.x * 8 + (threadIdx.x >> 5);
    int lane = threadIdx.x & 31;

    float v[4];
    #pragma unroll
    for (int j = 0; j < 4; j++) {
        int cc = j * 32 + lane;
        float s = g_bcr[cc];
        #pragma unroll
        for (int ks = 0; ks < HKS; ks++)
            s += g_hpart[ks][(size_t)n * NHC + cc];
        v[j] = s;
    }
    #pragma unroll
    for (int j = 0; j < 4; j++) {
        int cc = j * 32 + lane;
        if (cc >= NCLS && cc < NOUT)
            out[(size_t)NBOX * NCLS + (size_t)n * NREG + (cc - NCLS)] = v[j];
    }
    float cv = (lane < NCLS) ? v[0] : -3.4e38f;
    float m = cv;
    #pragma unroll
    for (int o = 16; o; o >>= 1) m = fmaxf(m, __shfl_xor_sync(0xffffffff, m, o));
    float e = (lane < NCLS) ? expf(cv - m) : 0.f;
    float ssum = e;
    #pragma unroll
    for (int o = 16; o; o >>= 1) ssum += __shfl_xor_sync(0xffffffff, ssum, o);
    if (lane < NCLS)
        out[(size_t)n * NCLS + lane] = e / ssum;
}

// ===================== launcher ============================================
extern "C" void kernel_launch(void* const* d_in, const int* in_sizes, int n_in,
                              void* d_out, int out_size)
{
    const float* feats = (const float*)d_in[0];
    const float* boxes = (const float*)d_in[1];
    const float* W1    = (const float*)d_in[2];
    const float* b1    = (const float*)d_in[3];
    const float* W2    = (const float*)d_in[4];
    const float* b2    = (const float*)d_in[5];
    const float* Wc    = (const float*)d_in[6];
    const float* bc    = (const float*)d_in[7];
    const float* Wr    = (const float*)d_in[8];
    const float* br    = (const float*)d_in[9];
    float* out = (float*)d_out;

    __half* w1h;  cudaGetSymbolAddress((void**)&w1h,  g_w1h);
    __half* w2h;  cudaGetSymbolAddress((void**)&w2h,  g_w2h);
    __half* ph;   cudaGetSymbolAddress((void**)&ph,   g_pooledh);
    __half* x1h;  cudaGetSymbolAddress((void**)&x1h,  g_x1h);
    __half* x2h;  cudaGetSymbolAddress((void**)&x2h,  g_x2h);

    cudaFuncSetAttribute(gemm_fp16_kernel,
                         cudaFuncAttributeMaxDynamicSharedMemorySize, GEMM_DSMEM);
    cudaFuncSetAttribute(gemm_heads_splitk_kernel,
                         cudaFuncAttributeMaxDynamicSharedMemorySize, GEMM_DSMEM);

    prep_kernel<<<NBOX + W1B + W2B + WCRB + 1, 256>>>(feats, boxes, W1, W2, Wc, bc, Wr, br);

    dim3 g1(D1 / BN, (NBOX + BM - 1) / BM);   // (32, 8)
    gemm_fp16_kernel<<<g1, GTHREADS, GEMM_DSMEM>>>(ph,  w1h, b1, x1h, NBOX, D1, DFLAT, 1, 1);
    gemm_fp16_kernel<<<g1, GTHREADS, GEMM_DSMEM>>>(x1h, w2h, b2, x2h, NBOX, D1, D1,    1, 1);

    gemm_heads_splitk_kernel<<<dim3(HKS, (NBOX + BM - 1) / BM), GTHREADS, GEMM_DSMEM>>>();
    heads_final_kernel<<<NBOX / 8, 256>>>(out);
}